// round 5
// baseline (speedup 1.0000x reference)
#include <cuda_runtime.h>
#include <math.h>

// ---------------- problem constants ----------------
#define TT   128
#define BB   32
#define NTB  4096            // T*B
#define HID  256
#define FEAT 512
#define FLAT 3136            // 64*7*7
#define NACT 6

// output layout (flattened tuple): logits[4096*6], v[4096], h[32*256], c[32*256]
#define OUT_V    24576
#define OUT_H    28672
#define OUT_C    36864

// ---------------- packed f32x2 helpers ----------------
typedef unsigned long long u64t;
__device__ __forceinline__ u64t pk2(float lo, float hi) {
    u64t r;
    asm("mov.b64 %0, {%1, %2};" : "=l"(r) : "f"(lo), "f"(hi));
    return r;
}
__device__ __forceinline__ void fma2(u64t& d, u64t a, u64t b) {
    asm("fma.rn.f32x2 %0, %1, %2, %0;" : "+l"(d) : "l"(a), "l"(b));
}
__device__ __forceinline__ float2 upk2(u64t v) {
    float2 f;
    asm("mov.b64 {%0, %1}, %2;" : "=f"(f.x), "=f"(f.y) : "l"(v));
    return f;
}

// ---------------- scratch ----------------
__device__ float g_c1[(size_t)NTB*32*20*20];
__device__ float g_c2[(size_t)NTB*64*9*9];
__device__ float g_c3[(size_t)NTB*64*7*7];
__device__ float g_feat[(size_t)NTB*FEAT];
__device__ float g_gx[(size_t)NTB*4*HID];
__device__ float g_hs[(size_t)NTB*HID];
__device__ float g_h[BB*HID];
__device__ unsigned g_bar;
__device__ unsigned g_exit;

// ======================================================================
// conv1: (n,3,84,84)/255 -> (n,32,20,20), k=8 s=4, relu.
// 224 threads; 200 active: thread = (h: 16-ch half) x (pg<100: 4 positions).
// Per kx: 4 weight LDS.128 -> 32 FMA2. Image rows loaded as float4.
// ======================================================================
#define C1_THREADS 224
#define C1_SMEM ((21168 + 6144) * 4)
__global__ void __launch_bounds__(C1_THREADS, 2)
conv1_kernel(const float* __restrict__ img,
             const float* __restrict__ w,
             const float* __restrict__ bias) {
    extern __shared__ float sm[];
    float* im = sm;           // 21168
    float* ws = sm + 21168;   // 6144, layout [c][ky][kx][co]
    int n = blockIdx.x;
    const float* src = img + (size_t)n * 21168;
    for (int i = threadIdx.x; i < 21168; i += C1_THREADS) im[i] = src[i];
    for (int i = threadIdx.x; i < 6144; i += C1_THREADS) {
        int co = i & 31; int rest = i >> 5;
        int kx = rest & 7; rest >>= 3;
        int ky = rest & 7; int c = rest >> 3;
        ws[i] = w[((co * 3 + c) * 8 + ky) * 8 + kx] * (1.0f / 255.0f);
    }
    __syncthreads();

    int t = threadIdx.x;
    if (t < 200) {
        int h = t / 100, pg = t % 100;
        int oy[4], ox[4];
#pragma unroll
        for (int s = 0; s < 4; s++) { int p = pg + 100 * s; oy[s] = p / 20; ox[s] = p % 20; }
        u64t acc[4][8];
        u64t z = pk2(0.f, 0.f);
#pragma unroll
        for (int s = 0; s < 4; s++)
#pragma unroll
            for (int q = 0; q < 8; q++) acc[s][q] = z;

        for (int c = 0; c < 3; c++) {
#pragma unroll
            for (int ky = 0; ky < 8; ky++) {
                float r[4][8];
#pragma unroll
                for (int s = 0; s < 4; s++) {
                    const float4* q4 = (const float4*)&im[(c * 84 + oy[s] * 4 + ky) * 84 + ox[s] * 4];
                    float4 A = q4[0], B = q4[1];
                    r[s][0]=A.x; r[s][1]=A.y; r[s][2]=A.z; r[s][3]=A.w;
                    r[s][4]=B.x; r[s][5]=B.y; r[s][6]=B.z; r[s][7]=B.w;
                }
#pragma unroll
                for (int kx = 0; kx < 8; kx++) {
                    const ulonglong2* wq = (const ulonglong2*)&ws[((c * 8 + ky) * 8 + kx) * 32 + h * 16];
                    ulonglong2 w0 = wq[0], w1 = wq[1], w2 = wq[2], w3 = wq[3];
#pragma unroll
                    for (int s = 0; s < 4; s++) {
                        u64t x = pk2(r[s][kx], r[s][kx]);
                        fma2(acc[s][0], x, w0.x); fma2(acc[s][1], x, w0.y);
                        fma2(acc[s][2], x, w1.x); fma2(acc[s][3], x, w1.y);
                        fma2(acc[s][4], x, w2.x); fma2(acc[s][5], x, w2.y);
                        fma2(acc[s][6], x, w3.x); fma2(acc[s][7], x, w3.y);
                    }
                }
            }
        }
        float* base = g_c1 + (size_t)n * 12800;
#pragma unroll
        for (int s = 0; s < 4; s++) {
            int pos = pg + 100 * s;
#pragma unroll
            for (int q = 0; q < 8; q++) {
                float2 v = upk2(acc[s][q]);
                int co = h * 16 + q * 2;
                base[(co+0) * 400 + pos] = fmaxf(v.x + bias[co+0], 0.f);
                base[(co+1) * 400 + pos] = fmaxf(v.y + bias[co+1], 0.f);
            }
        }
    }
}

// ======================================================================
// conv2: (n,32,20,20) -> (n,64,9,9), k=4 s=2, relu.
// 224 threads; 216 active: (cot<8: 8ch) x (p<27: 3 positions).
// Weights chunked (8 input ch, 32KB). Image loads as float2.
// ======================================================================
#define C2_THREADS 224
#define C2_SMEM ((12800 + 8192) * 4)
__global__ void __launch_bounds__(C2_THREADS, 2)
conv2_kernel(const float* __restrict__ w,
             const float* __restrict__ bias) {
    extern __shared__ float sm[];
    float* in = sm;            // 12800
    float* wc = sm + 12800;    // [cc=8][ky][kx][64]
    int n = blockIdx.x;
    const float* src = g_c1 + (size_t)n * 12800;
    for (int i = threadIdx.x; i < 12800; i += C2_THREADS) in[i] = src[i];

    int t = threadIdx.x;
    bool act = t < 216;
    int cot = t / 27, p = t % 27;
    int oy[3], ox[3];
#pragma unroll
    for (int s = 0; s < 3; s++) { int pp = p + 27 * s; oy[s] = pp / 9; ox[s] = pp % 9; }
    u64t acc[3][4];
    u64t z = pk2(0.f, 0.f);
#pragma unroll
    for (int s = 0; s < 3; s++)
#pragma unroll
        for (int q = 0; q < 4; q++) acc[s][q] = z;

    for (int ck = 0; ck < 4; ck++) {
        __syncthreads();
        for (int i = t; i < 8192; i += C2_THREADS) {
            int co = i & 63; int rest = i >> 6;
            int kx = rest & 3; rest >>= 2;
            int ky = rest & 3; int cc = rest >> 2;
            wc[i] = w[((co * 32 + ck * 8 + cc) * 4 + ky) * 4 + kx];
        }
        __syncthreads();
        if (act) {
            for (int cc = 0; cc < 8; cc++) {
                int c = ck * 8 + cc;
#pragma unroll
                for (int ky = 0; ky < 4; ky++) {
                    float r[3][4];
#pragma unroll
                    for (int s = 0; s < 3; s++) {
                        const float* bp = &in[(c * 20 + oy[s] * 2 + ky) * 20 + ox[s] * 2];
                        float2 f0 = *(const float2*)(bp);
                        float2 f1 = *(const float2*)(bp + 2);
                        r[s][0]=f0.x; r[s][1]=f0.y; r[s][2]=f1.x; r[s][3]=f1.y;
                    }
#pragma unroll
                    for (int kx = 0; kx < 4; kx++) {
                        const ulonglong2* wq = (const ulonglong2*)&wc[((cc * 4 + ky) * 4 + kx) * 64 + cot * 8];
                        ulonglong2 w0 = wq[0], w1 = wq[1];
#pragma unroll
                        for (int s = 0; s < 3; s++) {
                            u64t x = pk2(r[s][kx], r[s][kx]);
                            fma2(acc[s][0], x, w0.x); fma2(acc[s][1], x, w0.y);
                            fma2(acc[s][2], x, w1.x); fma2(acc[s][3], x, w1.y);
                        }
                    }
                }
            }
        }
    }
    if (act) {
        float* base = g_c2 + (size_t)n * 5184;
#pragma unroll
        for (int s = 0; s < 3; s++) {
            int pos = p + 27 * s;
#pragma unroll
            for (int q = 0; q < 4; q++) {
                float2 v = upk2(acc[s][q]);
                int co = cot * 8 + q * 2;
                base[(co+0) * 81 + pos] = fmaxf(v.x + bias[co+0], 0.f);
                base[(co+1) * 81 + pos] = fmaxf(v.y + bias[co+1], 0.f);
            }
        }
    }
}

// ======================================================================
// conv3: (n,64,9,9) -> (n,64,7,7), k=3 s=1, relu.
// 128 threads; 100 active: (cot<4: 16ch) x (p<25: 2 positions).
// Weights chunked (16 input ch, 37KB), 3 CTAs/SM.
// ======================================================================
#define C3_THREADS 128
#define C3_SMEM ((5184 + 9216) * 4)
__global__ void __launch_bounds__(C3_THREADS, 3)
conv3_kernel(const float* __restrict__ w,
             const float* __restrict__ bias) {
    extern __shared__ float sm[];
    float* in = sm;            // 5184
    float* wc = sm + 5184;     // [cc=16][ky][kx][64]
    int n = blockIdx.x;
    const float* src = g_c2 + (size_t)n * 5184;
    for (int i = threadIdx.x; i < 5184; i += C3_THREADS) in[i] = src[i];

    int t = threadIdx.x;
    bool act = t < 100;
    int cot = t / 25, p = t % 25;
    bool has2 = p < 24;
    int p2 = has2 ? p + 25 : p;
    int oy1 = p / 7, ox1 = p % 7;
    int oy2 = p2 / 7, ox2 = p2 % 7;
    u64t a1[8], a2[8];
    u64t z = pk2(0.f, 0.f);
#pragma unroll
    for (int i = 0; i < 8; i++) { a1[i] = z; a2[i] = z; }

    for (int ck = 0; ck < 4; ck++) {
        __syncthreads();
        for (int i = t; i < 9216; i += C3_THREADS) {
            int co = i & 63; int rest = i >> 6;
            int kx = rest % 3; rest /= 3;
            int ky = rest % 3; int cc = rest / 3;
            wc[i] = w[((co * 64 + ck * 16 + cc) * 3 + ky) * 3 + kx];
        }
        __syncthreads();
        if (act) {
            for (int cc = 0; cc < 16; cc++) {
                int c = ck * 16 + cc;
#pragma unroll
                for (int ky = 0; ky < 3; ky++) {
                    const float* b1 = &in[(c * 9 + oy1 + ky) * 9 + ox1];
                    const float* b2 = &in[(c * 9 + oy2 + ky) * 9 + ox2];
                    float r1[3], r2[3];
#pragma unroll
                    for (int kx = 0; kx < 3; kx++) { r1[kx] = b1[kx]; r2[kx] = b2[kx]; }
#pragma unroll
                    for (int kx = 0; kx < 3; kx++) {
                        const ulonglong2* wq = (const ulonglong2*)&wc[((cc * 3 + ky) * 3 + kx) * 64 + cot * 16];
                        ulonglong2 w0 = wq[0], w1 = wq[1], w2 = wq[2], w3 = wq[3];
                        u64t x1 = pk2(r1[kx], r1[kx]);
                        u64t x2 = pk2(r2[kx], r2[kx]);
                        fma2(a1[0], x1, w0.x); fma2(a1[1], x1, w0.y);
                        fma2(a1[2], x1, w1.x); fma2(a1[3], x1, w1.y);
                        fma2(a1[4], x1, w2.x); fma2(a1[5], x1, w2.y);
                        fma2(a1[6], x1, w3.x); fma2(a1[7], x1, w3.y);
                        fma2(a2[0], x2, w0.x); fma2(a2[1], x2, w0.y);
                        fma2(a2[2], x2, w1.x); fma2(a2[3], x2, w1.y);
                        fma2(a2[4], x2, w2.x); fma2(a2[5], x2, w2.y);
                        fma2(a2[6], x2, w3.x); fma2(a2[7], x2, w3.y);
                    }
                }
            }
        }
    }
    if (act) {
        float* base = g_c3 + (size_t)n * 3136;
#pragma unroll
        for (int q = 0; q < 8; q++) {
            float2 v1 = upk2(a1[q]), v2 = upk2(a2[q]);
            int co = cot * 16 + q * 2;
            float b0 = bias[co], b1v = bias[co + 1];
            base[(co+0) * 49 + p] = fmaxf(v1.x + b0, 0.f);
            base[(co+1) * 49 + p] = fmaxf(v1.y + b1v, 0.f);
            if (has2) {
                base[(co+0) * 49 + p + 25] = fmaxf(v2.x + b0, 0.f);
                base[(co+1) * 49 + p + 25] = fmaxf(v2.y + b1v, 0.f);
            }
        }
    }
}

// ======================================================================
// GEMM: C[M,N] = A[M,K] @ Bw[N,K]^T + b1 (+ b2), optional relu
// BM x 128 CTA tile (BM in {64,128}), BK=16, 256 threads, double-buffered.
// ======================================================================
template <int BM, bool RELU>
__global__ void __launch_bounds__(256)
gemm_kernel(const float* __restrict__ A,
            const float* __restrict__ Bw,
            const float* __restrict__ bias1,
            const float* __restrict__ bias2,
            float* __restrict__ C,
            int M, int N, int K) {
    constexpr int MI = BM / 16;        // rows per thread: 8 or 4
    __shared__ float As[2][16][BM + 4];
    __shared__ float Bs[2][16][132];
    int bm = blockIdx.y * BM, bn = blockIdx.x * 128;
    int t = threadIdx.x;
    int tx = t & 15, ty = t >> 4;
    int alr, alc;
    if (BM == 128) { alr = t >> 1; alc = (t & 1) * 8; }
    else           { alr = t >> 2; alc = (t & 3) * 4; }
    int blr = t >> 1, blc = (t & 1) * 8;

    u64t acc[MI][4];
    u64t z = pk2(0.f, 0.f);
#pragma unroll
    for (int i = 0; i < MI; i++)
#pragma unroll
        for (int j = 0; j < 4; j++) acc[i][j] = z;

    const float* Ap = A + (size_t)(bm + alr) * K + alc;
    const float* Bp = Bw + (size_t)(bn + blr) * K + blc;

    {
        float4 a0 = *(const float4*)(Ap);
        As[0][alc+0][alr]=a0.x; As[0][alc+1][alr]=a0.y; As[0][alc+2][alr]=a0.z; As[0][alc+3][alr]=a0.w;
        if (BM == 128) {
            float4 a1 = *(const float4*)(Ap + 4);
            As[0][alc+4][alr]=a1.x; As[0][alc+5][alr]=a1.y; As[0][alc+6][alr]=a1.z; As[0][alc+7][alr]=a1.w;
        }
        float4 b0 = *(const float4*)(Bp);
        float4 b1 = *(const float4*)(Bp + 4);
        Bs[0][blc+0][blr]=b0.x; Bs[0][blc+1][blr]=b0.y; Bs[0][blc+2][blr]=b0.z; Bs[0][blc+3][blr]=b0.w;
        Bs[0][blc+4][blr]=b1.x; Bs[0][blc+5][blr]=b1.y; Bs[0][blc+6][blr]=b1.z; Bs[0][blc+7][blr]=b1.w;
    }
    __syncthreads();

    int cur = 0;
    for (int k0 = 0; k0 < K; k0 += 16) {
        float4 a0, a1, b0, b1;
        bool more = (k0 + 16) < K;
        if (more) {
            a0 = *(const float4*)(Ap + k0 + 16);
            if (BM == 128) a1 = *(const float4*)(Ap + k0 + 20);
            b0 = *(const float4*)(Bp + k0 + 16);
            b1 = *(const float4*)(Bp + k0 + 20);
        }
#pragma unroll
        for (int kk = 0; kk < 16; kk++) {
            float a[MI];
            *(float4*)&a[0] = *(const float4*)&As[cur][kk][ty * MI];
            if (BM == 128)
                *(float4*)&a[4] = *(const float4*)&As[cur][kk][ty * MI + 4];
            const ulonglong2* bp2 = (const ulonglong2*)&Bs[cur][kk][tx * 8];
            ulonglong2 bb0 = bp2[0], bb1 = bp2[1];
#pragma unroll
            for (int i = 0; i < MI; i++) {
                u64t aa = pk2(a[i], a[i]);
                fma2(acc[i][0], aa, bb0.x);
                fma2(acc[i][1], aa, bb0.y);
                fma2(acc[i][2], aa, bb1.x);
                fma2(acc[i][3], aa, bb1.y);
            }
        }
        if (more) {
            int nxt = cur ^ 1;
            As[nxt][alc+0][alr]=a0.x; As[nxt][alc+1][alr]=a0.y; As[nxt][alc+2][alr]=a0.z; As[nxt][alc+3][alr]=a0.w;
            if (BM == 128) {
                As[nxt][alc+4][alr]=a1.x; As[nxt][alc+5][alr]=a1.y; As[nxt][alc+6][alr]=a1.z; As[nxt][alc+7][alr]=a1.w;
            }
            Bs[nxt][blc+0][blr]=b0.x; Bs[nxt][blc+1][blr]=b0.y; Bs[nxt][blc+2][blr]=b0.z; Bs[nxt][blc+3][blr]=b0.w;
            Bs[nxt][blc+4][blr]=b1.x; Bs[nxt][blc+5][blr]=b1.y; Bs[nxt][blc+6][blr]=b1.z; Bs[nxt][blc+7][blr]=b1.w;
            __syncthreads();
            cur = nxt;
        }
    }

#pragma unroll
    for (int i = 0; i < MI; i++) {
        int row = bm + ty * MI + i;
#pragma unroll
        for (int j = 0; j < 4; j++) {
            float2 v = upk2(acc[i][j]);
            int col = bn + tx * 8 + j * 2;
            float r0 = v.x + bias1[col];
            float r1 = v.y + bias1[col + 1];
            if (bias2) { r0 += bias2[col]; r1 += bias2[col + 1]; }
            if (RELU) { r0 = fmaxf(r0, 0.f); r1 = fmaxf(r1, 0.f); }
            C[(size_t)row * N + col]     = r0;
            C[(size_t)row * N + col + 1] = r1;
        }
    }
}

// ======================================================================
// persistent LSTM: 128 CTAs, each owns 2 hidden units.
// ======================================================================
#define NBLK 128
#define LSTM_SMEM ((2048 + 8224 + 64 + 576) * 4)
__device__ __forceinline__ float sigmoidf(float x) { return 1.f / (1.f + expf(-x)); }

__global__ void __launch_bounds__(256)
lstm_kernel(const float* __restrict__ done,
            const float* __restrict__ h0,
            const float* __restrict__ c0,
            const float* __restrict__ whh,
            float* __restrict__ out) {
    extern __shared__ float sm[];
    float* w_s = sm;             // [k=256][r=8]
    float* h_s = sm + 2048;      // [32][257]
    float* c_s = h_s + 8224;     // [64]
    float* p_s = c_s + 64;       // [2][32][9]
    int t = threadIdx.x, blk = blockIdx.x;
    int j0 = blk * 2;

    for (int i = t; i < 2048; i += 256) {
        int k = i >> 3, r = i & 7;
        int q = r >> 1, jj = r & 1;
        w_s[i] = whh[(size_t)(q * HID + j0 + jj) * HID + k];
    }
    if (t < 64) {
        int b = t >> 1, jj = t & 1;
        c_s[t] = c0[b * HID + j0 + jj];
    }
    __syncthreads();

    int u = t & 127, half = t >> 7;
    int gb = u & 31, rq = u >> 5;
    unsigned target = 0;

    for (int step = 0; step < TT; step++) {
        float2 acc0;
        if (half == 0)
            acc0 = *(const float2*)&g_gx[(size_t)(step * BB + gb) * 4 * HID + rq * HID + j0];
        else
            acc0 = make_float2(0.f, 0.f);
        u64t accp = pk2(acc0.x, acc0.y);

        const float* hsrc = (step == 0) ? h0 : g_h;
        for (int i = t; i < BB * HID; i += 256) {
            int b = i >> 8;
            h_s[b * 257 + (i & 255)] = hsrc[i] * (1.0f - __ldg(&done[step * BB + b]));
        }
        __syncthreads();

        {
            const float* hp = &h_s[gb * 257 + half * 128];
            const float* wp = &w_s[(half * 128) * 8 + rq * 2];
#pragma unroll 8
            for (int k = 0; k < 128; k++) {
                float hv = hp[k];
                u64t hh = pk2(hv, hv);
                u64t wv = *(const u64t*)&wp[k * 8];
                fma2(accp, hh, wv);
            }
            float2 r = upk2(accp);
            float* pp = &p_s[half * 288 + gb * 9 + rq * 2];
            pp[0] = r.x; pp[1] = r.y;
        }
        __syncthreads();

        if (t < 64) {
            int b = t >> 1, jj = t & 1;
            float m = 1.0f - __ldg(&done[step * BB + b]);
            const float* p0 = &p_s[b * 9];
            const float* p1 = &p_s[288 + b * 9];
            float gi = p0[0 + jj] + p1[0 + jj];
            float gf = p0[2 + jj] + p1[2 + jj];
            float gg = p0[4 + jj] + p1[4 + jj];
            float go = p0[6 + jj] + p1[6 + jj];
            float I = sigmoidf(gi);
            float F = sigmoidf(gf);
            float G = tanhf(gg);
            float O = sigmoidf(go);
            float c_new = F * (m * c_s[t]) + I * G;
            c_s[t] = c_new;
            float h_new = O * tanhf(c_new);
            g_h[b * HID + j0 + jj] = h_new;
            g_hs[(size_t)(step * BB + b) * HID + j0 + jj] = h_new;
            if (step == TT - 1) {
                out[OUT_H + b * HID + j0 + jj] = h_new;
                out[OUT_C + b * HID + j0 + jj] = c_new;
            }
        }
        __threadfence();
        __syncthreads();
        if (t == 0) {
            atomicAdd(&g_bar, 1u);
            target += NBLK;
            while (*(volatile unsigned*)&g_bar < target) { }
        }
        __syncthreads();
    }

    if (t == 0) {
        unsigned v = atomicAdd(&g_exit, 1u);
        if (v == NBLK - 1) {
            atomicExch(&g_exit, 0u);
            atomicExch(&g_bar, 0u);
            __threadfence();
        }
    }
}

// ======================================================================
// heads
// ======================================================================
__global__ void heads_kernel(const float* __restrict__ pw,
                             const float* __restrict__ pb,
                             const float* __restrict__ vw,
                             const float* __restrict__ vb,
                             float* __restrict__ out) {
    __shared__ float ws[7 * 256];
    int t = threadIdx.x;
    for (int i = t; i < 6 * 256; i += 256) ws[i] = pw[i];
    if (t < 256) ws[1536 + t] = vw[t];
    __syncthreads();

    int warp = t >> 5, lane = t & 31;
    int row = blockIdx.x * 8 + warp;
    const float* hrow = g_hs + (size_t)row * 256;
    float p[7];
#pragma unroll
    for (int a = 0; a < 7; a++) p[a] = 0.f;
    for (int k = lane; k < 256; k += 32) {
        float hv = hrow[k];
#pragma unroll
        for (int a = 0; a < 7; a++) p[a] += hv * ws[a * 256 + k];
    }
#pragma unroll
    for (int a = 0; a < 7; a++)
#pragma unroll
        for (int off = 16; off; off >>= 1)
            p[a] += __shfl_xor_sync(0xffffffffu, p[a], off);
    if (lane == 0) {
#pragma unroll
        for (int a = 0; a < 6; a++) out[(size_t)row * 6 + a] = p[a] + pb[a];
        out[OUT_V + row] = p[6] + vb[0];
    }
}

// ======================================================================
// launch
// ======================================================================
extern "C" void kernel_launch(void* const* d_in, const int* in_sizes, int n_in,
                              void* d_out, int out_size) {
    const float* image = (const float*)d_in[0];
    const float* done  = (const float*)d_in[1];
    const float* h0    = (const float*)d_in[2];
    const float* c0    = (const float*)d_in[3];
    const float* c1w   = (const float*)d_in[4];
    const float* c1b   = (const float*)d_in[5];
    const float* c2w   = (const float*)d_in[6];
    const float* c2b   = (const float*)d_in[7];
    const float* c3w   = (const float*)d_in[8];
    const float* c3b   = (const float*)d_in[9];
    const float* fcw   = (const float*)d_in[10];
    const float* fcb   = (const float*)d_in[11];
    const float* wih   = (const float*)d_in[12];
    const float* whh   = (const float*)d_in[13];
    const float* bih   = (const float*)d_in[14];
    const float* bhh   = (const float*)d_in[15];
    const float* polw  = (const float*)d_in[16];
    const float* polb  = (const float*)d_in[17];
    const float* valw  = (const float*)d_in[18];
    const float* valb  = (const float*)d_in[19];
    float* out = (float*)d_out;

    cudaFuncSetAttribute(conv1_kernel, cudaFuncAttributeMaxDynamicSharedMemorySize, C1_SMEM);
    cudaFuncSetAttribute(conv2_kernel, cudaFuncAttributeMaxDynamicSharedMemorySize, C2_SMEM);
    cudaFuncSetAttribute(conv3_kernel, cudaFuncAttributeMaxDynamicSharedMemorySize, C3_SMEM);
    cudaFuncSetAttribute(lstm_kernel,  cudaFuncAttributeMaxDynamicSharedMemorySize, LSTM_SMEM);

    void *p_c3, *p_feat, *p_gx;
    cudaGetSymbolAddress(&p_c3, g_c3);
    cudaGetSymbolAddress(&p_feat, g_feat);
    cudaGetSymbolAddress(&p_gx, g_gx);

    conv1_kernel<<<NTB, C1_THREADS, C1_SMEM>>>(image, c1w, c1b);
    conv2_kernel<<<NTB, C2_THREADS, C2_SMEM>>>(c2w, c2b);
    conv3_kernel<<<NTB, C3_THREADS, C3_SMEM>>>(c3w, c3b);

    // feats = relu(flat @ fc_w^T + fc_b)   [4096,512] -- 64x128 tiles -> 256 CTAs
    gemm_kernel<64, true><<<dim3(FEAT / 128, NTB / 64), 256>>>(
        (const float*)p_c3, fcw, fcb, nullptr, (float*)p_feat, NTB, FEAT, FLAT);

    // gates_x = feats @ w_ih^T + b_ih + b_hh   [4096,1024] -- 256 CTAs
    gemm_kernel<128, false><<<dim3((4 * HID) / 128, NTB / 128), 256>>>(
        (const float*)p_feat, wih, bih, bhh, (float*)p_gx, NTB, 4 * HID, FEAT);

    lstm_kernel<<<NBLK, 256, LSTM_SMEM>>>(done, h0, c0, whh, out);

    heads_kernel<<<NTB / 8, 256>>>(polw, polb, valw, valb, out);
}

// round 6
// speedup vs baseline: 1.1217x; 1.1217x over previous
#include <cuda_runtime.h>
#include <math.h>

// ---------------- problem constants ----------------
#define TT   128
#define BB   32
#define NTB  4096            // T*B
#define HID  256
#define FEAT 512
#define FLAT 3136            // 64*7*7
#define NACT 6

// output layout: logits[4096*6], v[4096], h[32*256], c[32*256]
#define OUT_V    24576
#define OUT_H    28672
#define OUT_C    36864

// ---------------- packed f32x2 helpers ----------------
typedef unsigned long long u64t;
__device__ __forceinline__ u64t pk2(float lo, float hi) {
    u64t r;
    asm("mov.b64 %0, {%1, %2};" : "=l"(r) : "f"(lo), "f"(hi));
    return r;
}
__device__ __forceinline__ void fma2(u64t& d, u64t a, u64t b) {
    asm("fma.rn.f32x2 %0, %1, %2, %0;" : "+l"(d) : "l"(a), "l"(b));
}
__device__ __forceinline__ float2 upk2(u64t v) {
    float2 f;
    asm("mov.b64 {%0, %1}, %2;" : "=f"(f.x), "=f"(f.y) : "l"(v));
    return f;
}

// ---------------- tf32 helpers ----------------
__device__ __forceinline__ float to_tf32(float x) {
    unsigned u;
    asm("cvt.rna.tf32.f32 %0, %1;" : "=r"(u) : "f"(x));
    return __uint_as_float(u);
}
__device__ __forceinline__ void mma_tf32(float c[4], const unsigned a[4], const unsigned b[2]) {
    asm volatile(
        "mma.sync.aligned.m16n8k8.row.col.f32.tf32.tf32.f32 "
        "{%0,%1,%2,%3}, {%4,%5,%6,%7}, {%8,%9}, {%0,%1,%2,%3};"
        : "+f"(c[0]), "+f"(c[1]), "+f"(c[2]), "+f"(c[3])
        : "r"(a[0]), "r"(a[1]), "r"(a[2]), "r"(a[3]), "r"(b[0]), "r"(b[1]));
}

// ---------------- scratch ----------------
__device__ float g_c1[(size_t)NTB*32*20*20];
__device__ float g_c2[(size_t)NTB*64*9*9];
__device__ float g_c3[(size_t)NTB*64*7*7];
__device__ float g_feat[(size_t)NTB*FEAT];
__device__ float g_gx[(size_t)NTB*4*HID];
__device__ float g_hs[(size_t)NTB*HID];
__device__ float g_h[BB*HID];
__device__ unsigned g_bar;
__device__ unsigned g_exit;

// ======================================================================
// conv1: (n,3,84,84)/255 -> (n,32,20,20), k=8 s=4, relu.  (round-5 version)
// ======================================================================
#define C1_THREADS 224
#define C1_SMEM ((21168 + 6144) * 4)
__global__ void __launch_bounds__(C1_THREADS, 2)
conv1_kernel(const float* __restrict__ img,
             const float* __restrict__ w,
             const float* __restrict__ bias) {
    extern __shared__ float sm[];
    float* im = sm;           // 21168
    float* ws = sm + 21168;   // 6144, layout [c][ky][kx][co]
    int n = blockIdx.x;
    const float* src = img + (size_t)n * 21168;
    for (int i = threadIdx.x; i < 21168; i += C1_THREADS) im[i] = src[i];
    for (int i = threadIdx.x; i < 6144; i += C1_THREADS) {
        int co = i & 31; int rest = i >> 5;
        int kx = rest & 7; rest >>= 3;
        int ky = rest & 7; int c = rest >> 3;
        ws[i] = w[((co * 3 + c) * 8 + ky) * 8 + kx] * (1.0f / 255.0f);
    }
    __syncthreads();

    int t = threadIdx.x;
    if (t < 200) {
        int h = t / 100, pg = t % 100;
        int oy[4], ox[4];
#pragma unroll
        for (int s = 0; s < 4; s++) { int p = pg + 100 * s; oy[s] = p / 20; ox[s] = p % 20; }
        u64t acc[4][8];
        u64t z = pk2(0.f, 0.f);
#pragma unroll
        for (int s = 0; s < 4; s++)
#pragma unroll
            for (int q = 0; q < 8; q++) acc[s][q] = z;

        for (int c = 0; c < 3; c++) {
#pragma unroll
            for (int ky = 0; ky < 8; ky++) {
                float r[4][8];
#pragma unroll
                for (int s = 0; s < 4; s++) {
                    const float4* q4 = (const float4*)&im[(c * 84 + oy[s] * 4 + ky) * 84 + ox[s] * 4];
                    float4 A = q4[0], B = q4[1];
                    r[s][0]=A.x; r[s][1]=A.y; r[s][2]=A.z; r[s][3]=A.w;
                    r[s][4]=B.x; r[s][5]=B.y; r[s][6]=B.z; r[s][7]=B.w;
                }
#pragma unroll
                for (int kx = 0; kx < 8; kx++) {
                    const ulonglong2* wq = (const ulonglong2*)&ws[((c * 8 + ky) * 8 + kx) * 32 + h * 16];
                    ulonglong2 w0 = wq[0], w1 = wq[1], w2 = wq[2], w3 = wq[3];
#pragma unroll
                    for (int s = 0; s < 4; s++) {
                        u64t x = pk2(r[s][kx], r[s][kx]);
                        fma2(acc[s][0], x, w0.x); fma2(acc[s][1], x, w0.y);
                        fma2(acc[s][2], x, w1.x); fma2(acc[s][3], x, w1.y);
                        fma2(acc[s][4], x, w2.x); fma2(acc[s][5], x, w2.y);
                        fma2(acc[s][6], x, w3.x); fma2(acc[s][7], x, w3.y);
                    }
                }
            }
        }
        float* base = g_c1 + (size_t)n * 12800;
#pragma unroll
        for (int s = 0; s < 4; s++) {
            int pos = pg + 100 * s;
#pragma unroll
            for (int q = 0; q < 8; q++) {
                float2 v = upk2(acc[s][q]);
                int co = h * 16 + q * 2;
                base[(co+0) * 400 + pos] = fmaxf(v.x + bias[co+0], 0.f);
                base[(co+1) * 400 + pos] = fmaxf(v.y + bias[co+1], 0.f);
            }
        }
    }
}

// ======================================================================
// conv2: (n,32,20,20) -> (n,64,9,9), k=4 s=2, relu.  (round-5 version)
// ======================================================================
#define C2_THREADS 224
#define C2_SMEM ((12800 + 8192) * 4)
__global__ void __launch_bounds__(C2_THREADS, 2)
conv2_kernel(const float* __restrict__ w,
             const float* __restrict__ bias) {
    extern __shared__ float sm[];
    float* in = sm;            // 12800
    float* wc = sm + 12800;    // [cc=8][ky][kx][64]
    int n = blockIdx.x;
    const float* src = g_c1 + (size_t)n * 12800;
    for (int i = threadIdx.x; i < 12800; i += C2_THREADS) in[i] = src[i];

    int t = threadIdx.x;
    bool act = t < 216;
    int cot = t / 27, p = t % 27;
    int oy[3], ox[3];
#pragma unroll
    for (int s = 0; s < 3; s++) { int pp = p + 27 * s; oy[s] = pp / 9; ox[s] = pp % 9; }
    u64t acc[3][4];
    u64t z = pk2(0.f, 0.f);
#pragma unroll
    for (int s = 0; s < 3; s++)
#pragma unroll
        for (int q = 0; q < 4; q++) acc[s][q] = z;

    for (int ck = 0; ck < 4; ck++) {
        __syncthreads();
        for (int i = t; i < 8192; i += C2_THREADS) {
            int co = i & 63; int rest = i >> 6;
            int kx = rest & 3; rest >>= 2;
            int ky = rest & 3; int cc = rest >> 2;
            wc[i] = w[((co * 32 + ck * 8 + cc) * 4 + ky) * 4 + kx];
        }
        __syncthreads();
        if (act) {
            for (int cc = 0; cc < 8; cc++) {
                int c = ck * 8 + cc;
#pragma unroll
                for (int ky = 0; ky < 4; ky++) {
                    float r[3][4];
#pragma unroll
                    for (int s = 0; s < 3; s++) {
                        const float* bp = &in[(c * 20 + oy[s] * 2 + ky) * 20 + ox[s] * 2];
                        float2 f0 = *(const float2*)(bp);
                        float2 f1 = *(const float2*)(bp + 2);
                        r[s][0]=f0.x; r[s][1]=f0.y; r[s][2]=f1.x; r[s][3]=f1.y;
                    }
#pragma unroll
                    for (int kx = 0; kx < 4; kx++) {
                        const ulonglong2* wq = (const ulonglong2*)&wc[((cc * 4 + ky) * 4 + kx) * 64 + cot * 8];
                        ulonglong2 w0 = wq[0], w1 = wq[1];
#pragma unroll
                        for (int s = 0; s < 3; s++) {
                            u64t x = pk2(r[s][kx], r[s][kx]);
                            fma2(acc[s][0], x, w0.x); fma2(acc[s][1], x, w0.y);
                            fma2(acc[s][2], x, w1.x); fma2(acc[s][3], x, w1.y);
                        }
                    }
                }
            }
        }
    }
    if (act) {
        float* base = g_c2 + (size_t)n * 5184;
#pragma unroll
        for (int s = 0; s < 3; s++) {
            int pos = p + 27 * s;
#pragma unroll
            for (int q = 0; q < 4; q++) {
                float2 v = upk2(acc[s][q]);
                int co = cot * 8 + q * 2;
                base[(co+0) * 81 + pos] = fmaxf(v.x + bias[co+0], 0.f);
                base[(co+1) * 81 + pos] = fmaxf(v.y + bias[co+1], 0.f);
            }
        }
    }
}

// ======================================================================
// conv3: (n,64,9,9) -> (n,64,7,7), k=3 s=1, relu.  (round-5 version)
// ======================================================================
#define C3_THREADS 128
#define C3_SMEM ((5184 + 9216) * 4)
__global__ void __launch_bounds__(C3_THREADS, 3)
conv3_kernel(const float* __restrict__ w,
             const float* __restrict__ bias) {
    extern __shared__ float sm[];
    float* in = sm;            // 5184
    float* wc = sm + 5184;     // [cc=16][ky][kx][64]
    int n = blockIdx.x;
    const float* src = g_c2 + (size_t)n * 5184;
    for (int i = threadIdx.x; i < 5184; i += C3_THREADS) in[i] = src[i];

    int t = threadIdx.x;
    bool act = t < 100;
    int cot = t / 25, p = t % 25;
    bool has2 = p < 24;
    int p2 = has2 ? p + 25 : p;
    int oy1 = p / 7, ox1 = p % 7;
    int oy2 = p2 / 7, ox2 = p2 % 7;
    u64t a1[8], a2[8];
    u64t z = pk2(0.f, 0.f);
#pragma unroll
    for (int i = 0; i < 8; i++) { a1[i] = z; a2[i] = z; }

    for (int ck = 0; ck < 4; ck++) {
        __syncthreads();
        for (int i = t; i < 9216; i += C3_THREADS) {
            int co = i & 63; int rest = i >> 6;
            int kx = rest % 3; rest /= 3;
            int ky = rest % 3; int cc = rest / 3;
            wc[i] = w[((co * 64 + ck * 16 + cc) * 3 + ky) * 3 + kx];
        }
        __syncthreads();
        if (act) {
            for (int cc = 0; cc < 16; cc++) {
                int c = ck * 16 + cc;
#pragma unroll
                for (int ky = 0; ky < 3; ky++) {
                    const float* b1 = &in[(c * 9 + oy1 + ky) * 9 + ox1];
                    const float* b2 = &in[(c * 9 + oy2 + ky) * 9 + ox2];
                    float r1[3], r2[3];
#pragma unroll
                    for (int kx = 0; kx < 3; kx++) { r1[kx] = b1[kx]; r2[kx] = b2[kx]; }
#pragma unroll
                    for (int kx = 0; kx < 3; kx++) {
                        const ulonglong2* wq = (const ulonglong2*)&wc[((cc * 3 + ky) * 3 + kx) * 64 + cot * 16];
                        ulonglong2 w0 = wq[0], w1 = wq[1], w2 = wq[2], w3 = wq[3];
                        u64t x1 = pk2(r1[kx], r1[kx]);
                        u64t x2 = pk2(r2[kx], r2[kx]);
                        fma2(a1[0], x1, w0.x); fma2(a1[1], x1, w0.y);
                        fma2(a1[2], x1, w1.x); fma2(a1[3], x1, w1.y);
                        fma2(a1[4], x1, w2.x); fma2(a1[5], x1, w2.y);
                        fma2(a1[6], x1, w3.x); fma2(a1[7], x1, w3.y);
                        fma2(a2[0], x2, w0.x); fma2(a2[1], x2, w0.y);
                        fma2(a2[2], x2, w1.x); fma2(a2[3], x2, w1.y);
                        fma2(a2[4], x2, w2.x); fma2(a2[5], x2, w2.y);
                        fma2(a2[6], x2, w3.x); fma2(a2[7], x2, w3.y);
                    }
                }
            }
        }
    }
    if (act) {
        float* base = g_c3 + (size_t)n * 3136;
#pragma unroll
        for (int q = 0; q < 8; q++) {
            float2 v1 = upk2(a1[q]), v2 = upk2(a2[q]);
            int co = cot * 16 + q * 2;
            float b0 = bias[co], b1v = bias[co + 1];
            base[(co+0) * 49 + p] = fmaxf(v1.x + b0, 0.f);
            base[(co+1) * 49 + p] = fmaxf(v1.y + b1v, 0.f);
            if (has2) {
                base[(co+0) * 49 + p + 25] = fmaxf(v2.x + b0, 0.f);
                base[(co+1) * 49 + p + 25] = fmaxf(v2.y + b1v, 0.f);
            }
        }
    }
}

// ======================================================================
// tf32 tensor-core GEMM: C[M,N] = A[M,K] @ Bw[N,K]^T + b1 (+b2), opt relu
// 128x128 CTA, BK=16, 256 threads (8 warps: 4M x 2N, warp tile 32x64),
// mma.sync.m16n8k8.tf32, double-buffered smem, cvt-to-tf32 at fill.
// Smem row stride 136 (k-row offsets = 8 mod 32 banks -> conflict-free frags).
// ======================================================================
template <bool RELU>
__global__ void __launch_bounds__(256)
gemm_tf32_kernel(const float* __restrict__ A,
                 const float* __restrict__ Bw,
                 const float* __restrict__ bias1,
                 const float* __restrict__ bias2,
                 float* __restrict__ C,
                 int M, int N, int K) {
    __shared__ float As[2][16][136];
    __shared__ float Bs[2][16][136];
    int bm = blockIdx.y * 128, bn = blockIdx.x * 128;
    int t = threadIdx.x;
    int wid = t >> 5, lane = t & 31;
    int gid = lane >> 2, tid4 = lane & 3;
    int wm = (wid >> 1) * 32;    // warp row offset (4 warps along M)
    int wn = (wid & 1) * 64;     // warp col offset (2 warps along N)
    int lr = t >> 1, lc = (t & 1) * 8;

    float c[2][8][4];
#pragma unroll
    for (int mt = 0; mt < 2; mt++)
#pragma unroll
        for (int nt = 0; nt < 8; nt++)
#pragma unroll
            for (int q = 0; q < 4; q++) c[mt][nt][q] = 0.f;

    const float* Ap = A + (size_t)(bm + lr) * K + lc;
    const float* Bp = Bw + (size_t)(bn + lr) * K + lc;

    // preload tile 0 (convert to tf32 at store)
    {
        float4 a0 = *(const float4*)(Ap);
        float4 a1 = *(const float4*)(Ap + 4);
        float4 b0 = *(const float4*)(Bp);
        float4 b1 = *(const float4*)(Bp + 4);
        As[0][lc+0][lr]=to_tf32(a0.x); As[0][lc+1][lr]=to_tf32(a0.y);
        As[0][lc+2][lr]=to_tf32(a0.z); As[0][lc+3][lr]=to_tf32(a0.w);
        As[0][lc+4][lr]=to_tf32(a1.x); As[0][lc+5][lr]=to_tf32(a1.y);
        As[0][lc+6][lr]=to_tf32(a1.z); As[0][lc+7][lr]=to_tf32(a1.w);
        Bs[0][lc+0][lr]=to_tf32(b0.x); Bs[0][lc+1][lr]=to_tf32(b0.y);
        Bs[0][lc+2][lr]=to_tf32(b0.z); Bs[0][lc+3][lr]=to_tf32(b0.w);
        Bs[0][lc+4][lr]=to_tf32(b1.x); Bs[0][lc+5][lr]=to_tf32(b1.y);
        Bs[0][lc+6][lr]=to_tf32(b1.z); Bs[0][lc+7][lr]=to_tf32(b1.w);
    }
    __syncthreads();

    int cur = 0;
    for (int k0 = 0; k0 < K; k0 += 16) {
        float4 a0, a1, b0, b1;
        bool more = (k0 + 16) < K;
        if (more) {
            a0 = *(const float4*)(Ap + k0 + 16);
            a1 = *(const float4*)(Ap + k0 + 20);
            b0 = *(const float4*)(Bp + k0 + 16);
            b1 = *(const float4*)(Bp + k0 + 20);
        }
#pragma unroll
        for (int ks = 0; ks < 2; ks++) {
            int kb = ks * 8;
            unsigned af[2][4];
#pragma unroll
            for (int mt = 0; mt < 2; mt++) {
                int m = wm + mt * 16 + gid;
                af[mt][0] = __float_as_uint(As[cur][kb + tid4    ][m]);
                af[mt][1] = __float_as_uint(As[cur][kb + tid4    ][m + 8]);
                af[mt][2] = __float_as_uint(As[cur][kb + tid4 + 4][m]);
                af[mt][3] = __float_as_uint(As[cur][kb + tid4 + 4][m + 8]);
            }
            unsigned bf[8][2];
#pragma unroll
            for (int nt = 0; nt < 8; nt++) {
                int nn = wn + nt * 8 + gid;
                bf[nt][0] = __float_as_uint(Bs[cur][kb + tid4    ][nn]);
                bf[nt][1] = __float_as_uint(Bs[cur][kb + tid4 + 4][nn]);
            }
#pragma unroll
            for (int mt = 0; mt < 2; mt++)
#pragma unroll
                for (int nt = 0; nt < 8; nt++)
                    mma_tf32(c[mt][nt], af[mt], bf[nt]);
        }
        if (more) {
            int nxt = cur ^ 1;
            As[nxt][lc+0][lr]=to_tf32(a0.x); As[nxt][lc+1][lr]=to_tf32(a0.y);
            As[nxt][lc+2][lr]=to_tf32(a0.z); As[nxt][lc+3][lr]=to_tf32(a0.w);
            As[nxt][lc+4][lr]=to_tf32(a1.x); As[nxt][lc+5][lr]=to_tf32(a1.y);
            As[nxt][lc+6][lr]=to_tf32(a1.z); As[nxt][lc+7][lr]=to_tf32(a1.w);
            Bs[nxt][lc+0][lr]=to_tf32(b0.x); Bs[nxt][lc+1][lr]=to_tf32(b0.y);
            Bs[nxt][lc+2][lr]=to_tf32(b0.z); Bs[nxt][lc+3][lr]=to_tf32(b0.w);
            Bs[nxt][lc+4][lr]=to_tf32(b1.x); Bs[nxt][lc+5][lr]=to_tf32(b1.y);
            Bs[nxt][lc+6][lr]=to_tf32(b1.z); Bs[nxt][lc+7][lr]=to_tf32(b1.w);
            __syncthreads();
            cur = nxt;
        }
    }

    // epilogue: c0,c1 -> (row, col..col+1); c2,c3 -> (row+8, ...)
#pragma unroll
    for (int mt = 0; mt < 2; mt++) {
        int row = bm + wm + mt * 16 + gid;
#pragma unroll
        for (int nt = 0; nt < 8; nt++) {
            int col = bn + wn + nt * 8 + tid4 * 2;
            float bv0 = bias1[col], bv1 = bias1[col + 1];
            if (bias2) { bv0 += bias2[col]; bv1 += bias2[col + 1]; }
            float r0 = c[mt][nt][0] + bv0;
            float r1 = c[mt][nt][1] + bv1;
            float r2 = c[mt][nt][2] + bv0;
            float r3 = c[mt][nt][3] + bv1;
            if (RELU) {
                r0 = fmaxf(r0, 0.f); r1 = fmaxf(r1, 0.f);
                r2 = fmaxf(r2, 0.f); r3 = fmaxf(r3, 0.f);
            }
            *(float2*)&C[(size_t)row * N + col]       = make_float2(r0, r1);
            *(float2*)&C[(size_t)(row + 8) * N + col] = make_float2(r2, r3);
        }
    }
}

// ======================================================================
// persistent LSTM: 128 CTAs, each owns 2 hidden units.
// ======================================================================
#define NBLK 128
#define LSTM_SMEM ((2048 + 8224 + 64 + 576) * 4)
__device__ __forceinline__ float sigmoidf(float x) { return 1.f / (1.f + expf(-x)); }

__global__ void __launch_bounds__(256)
lstm_kernel(const float* __restrict__ done,
            const float* __restrict__ h0,
            const float* __restrict__ c0,
            const float* __restrict__ whh,
            float* __restrict__ out) {
    extern __shared__ float sm[];
    float* w_s = sm;             // [k=256][r=8]
    float* h_s = sm + 2048;      // [32][257]
    float* c_s = h_s + 8224;     // [64]
    float* p_s = c_s + 64;       // [2][32][9]
    int t = threadIdx.x, blk = blockIdx.x;
    int j0 = blk * 2;

    for (int i = t; i < 2048; i += 256) {
        int k = i >> 3, r = i & 7;
        int q = r >> 1, jj = r & 1;
        w_s[i] = whh[(size_t)(q * HID + j0 + jj) * HID + k];
    }
    if (t < 64) {
        int b = t >> 1, jj = t & 1;
        c_s[t] = c0[b * HID + j0 + jj];
    }
    __syncthreads();

    int u = t & 127, half = t >> 7;
    int gb = u & 31, rq = u >> 5;
    unsigned target = 0;

    for (int step = 0; step < TT; step++) {
        float2 acc0;
        if (half == 0)
            acc0 = *(const float2*)&g_gx[(size_t)(step * BB + gb) * 4 * HID + rq * HID + j0];
        else
            acc0 = make_float2(0.f, 0.f);
        u64t accp = pk2(acc0.x, acc0.y);

        const float* hsrc = (step == 0) ? h0 : g_h;
        for (int i = t; i < BB * HID; i += 256) {
            int b = i >> 8;
            h_s[b * 257 + (i & 255)] = hsrc[i] * (1.0f - __ldg(&done[step * BB + b]));
        }
        __syncthreads();

        {
            const float* hp = &h_s[gb * 257 + half * 128];
            const float* wp = &w_s[(half * 128) * 8 + rq * 2];
#pragma unroll 8
            for (int k = 0; k < 128; k++) {
                float hv = hp[k];
                u64t hh = pk2(hv, hv);
                u64t wv = *(const u64t*)&wp[k * 8];
                fma2(accp, hh, wv);
            }
            float2 r = upk2(accp);
            float* pp = &p_s[half * 288 + gb * 9 + rq * 2];
            pp[0] = r.x; pp[1] = r.y;
        }
        __syncthreads();

        if (t < 64) {
            int b = t >> 1, jj = t & 1;
            float m = 1.0f - __ldg(&done[step * BB + b]);
            const float* p0 = &p_s[b * 9];
            const float* p1 = &p_s[288 + b * 9];
            float gi = p0[0 + jj] + p1[0 + jj];
            float gf = p0[2 + jj] + p1[2 + jj];
            float gg = p0[4 + jj] + p1[4 + jj];
            float go = p0[6 + jj] + p1[6 + jj];
            float I = sigmoidf(gi);
            float F = sigmoidf(gf);
            float G = tanhf(gg);
            float O = sigmoidf(go);
            float c_new = F * (m * c_s[t]) + I * G;
            c_s[t] = c_new;
            float h_new = O * tanhf(c_new);
            g_h[b * HID + j0 + jj] = h_new;
            g_hs[(size_t)(step * BB + b) * HID + j0 + jj] = h_new;
            if (step == TT - 1) {
                out[OUT_H + b * HID + j0 + jj] = h_new;
                out[OUT_C + b * HID + j0 + jj] = c_new;
            }
        }
        __threadfence();
        __syncthreads();
        if (t == 0) {
            atomicAdd(&g_bar, 1u);
            target += NBLK;
            while (*(volatile unsigned*)&g_bar < target) { }
        }
        __syncthreads();
    }

    if (t == 0) {
        unsigned v = atomicAdd(&g_exit, 1u);
        if (v == NBLK - 1) {
            atomicExch(&g_exit, 0u);
            atomicExch(&g_bar, 0u);
            __threadfence();
        }
    }
}

// ======================================================================
// heads
// ======================================================================
__global__ void heads_kernel(const float* __restrict__ pw,
                             const float* __restrict__ pb,
                             const float* __restrict__ vw,
                             const float* __restrict__ vb,
                             float* __restrict__ out) {
    __shared__ float ws[7 * 256];
    int t = threadIdx.x;
    for (int i = t; i < 6 * 256; i += 256) ws[i] = pw[i];
    if (t < 256) ws[1536 + t] = vw[t];
    __syncthreads();

    int warp = t >> 5, lane = t & 31;
    int row = blockIdx.x * 8 + warp;
    const float* hrow = g_hs + (size_t)row * 256;
    float p[7];
#pragma unroll
    for (int a = 0; a < 7; a++) p[a] = 0.f;
    for (int k = lane; k < 256; k += 32) {
        float hv = hrow[k];
#pragma unroll
        for (int a = 0; a < 7; a++) p[a] += hv * ws[a * 256 + k];
    }
#pragma unroll
    for (int a = 0; a < 7; a++)
#pragma unroll
        for (int off = 16; off; off >>= 1)
            p[a] += __shfl_xor_sync(0xffffffffu, p[a], off);
    if (lane == 0) {
#pragma unroll
        for (int a = 0; a < 6; a++) out[(size_t)row * 6 + a] = p[a] + pb[a];
        out[OUT_V + row] = p[6] + vb[0];
    }
}

// ======================================================================
// launch
// ======================================================================
extern "C" void kernel_launch(void* const* d_in, const int* in_sizes, int n_in,
                              void* d_out, int out_size) {
    const float* image = (const float*)d_in[0];
    const float* done  = (const float*)d_in[1];
    const float* h0    = (const float*)d_in[2];
    const float* c0    = (const float*)d_in[3];
    const float* c1w   = (const float*)d_in[4];
    const float* c1b   = (const float*)d_in[5];
    const float* c2w   = (const float*)d_in[6];
    const float* c2b   = (const float*)d_in[7];
    const float* c3w   = (const float*)d_in[8];
    const float* c3b   = (const float*)d_in[9];
    const float* fcw   = (const float*)d_in[10];
    const float* fcb   = (const float*)d_in[11];
    const float* wih   = (const float*)d_in[12];
    const float* whh   = (const float*)d_in[13];
    const float* bih   = (const float*)d_in[14];
    const float* bhh   = (const float*)d_in[15];
    const float* polw  = (const float*)d_in[16];
    const float* polb  = (const float*)d_in[17];
    const float* valw  = (const float*)d_in[18];
    const float* valb  = (const float*)d_in[19];
    float* out = (float*)d_out;

    cudaFuncSetAttribute(conv1_kernel, cudaFuncAttributeMaxDynamicSharedMemorySize, C1_SMEM);
    cudaFuncSetAttribute(conv2_kernel, cudaFuncAttributeMaxDynamicSharedMemorySize, C2_SMEM);
    cudaFuncSetAttribute(conv3_kernel, cudaFuncAttributeMaxDynamicSharedMemorySize, C3_SMEM);
    cudaFuncSetAttribute(lstm_kernel,  cudaFuncAttributeMaxDynamicSharedMemorySize, LSTM_SMEM);

    void *p_c3, *p_feat, *p_gx;
    cudaGetSymbolAddress(&p_c3, g_c3);
    cudaGetSymbolAddress(&p_feat, g_feat);
    cudaGetSymbolAddress(&p_gx, g_gx);

    conv1_kernel<<<NTB, C1_THREADS, C1_SMEM>>>(image, c1w, c1b);
    conv2_kernel<<<NTB, C2_THREADS, C2_SMEM>>>(c2w, c2b);
    conv3_kernel<<<NTB, C3_THREADS, C3_SMEM>>>(c3w, c3b);

    // feats = relu(flat @ fc_w^T + fc_b)   [4096,512]  (tf32 tensor cores)
    gemm_tf32_kernel<true><<<dim3(FEAT / 128, NTB / 128), 256>>>(
        (const float*)p_c3, fcw, fcb, nullptr, (float*)p_feat, NTB, FEAT, FLAT);

    // gates_x = feats @ w_ih^T + b_ih + b_hh   [4096,1024]  (tf32 tensor cores)
    gemm_tf32_kernel<false><<<dim3((4 * HID) / 128, NTB / 128), 256>>>(
        (const float*)p_feat, wih, bih, bhh, (float*)p_gx, NTB, 4 * HID, FEAT);

    lstm_kernel<<<NBLK, 256, LSTM_SMEM>>>(done, h0, c0, whh, out);

    heads_kernel<<<NTB / 8, 256>>>(polw, polb, valw, valb, out);
}